// round 3
// baseline (speedup 1.0000x reference)
#include <cuda_runtime.h>
#include <math.h>

#define NPROP 1000
#define NCLS  91
#define TOPK  100
#define NPAD  1024
#define SCORE_TH 0.05f
#define NMS_TH   0.5f
#define MIN_SIZE 1.0f
#define BBOX_CLIP 4.1351665567423f   /* log(1000/16) */

__device__ __forceinline__ float read_dim(const void* p) {
    // image_h / image_w may arrive as int32, int64 (low word), or float32.
    int iv = *(const int*)p;
    if (iv >= 1 && iv <= 100000) return (float)iv;        // int32 / int64 low word
    float fv = __int_as_float(iv);
    if (fv >= 1.0f && fv <= 100000.0f) return fv;          // float32
    return (float)iv;                                       // fallback
}

__global__ __launch_bounds__(NPAD, 1)
void roi_heads_kernel(const float* __restrict__ class_logit,   // [N, C]
                      const float* __restrict__ box_reg,       // [N, C*4]
                      const float* __restrict__ proposal,      // [N, 4]
                      const void*  __restrict__ p_img_h,
                      const void*  __restrict__ p_img_w,
                      float* __restrict__ out, int out_size)
{
    const int c   = blockIdx.x + 1;     // foreground class 1..90
    const int tid = threadIdx.x;

    __shared__ float s_box[NPROP * 4];   // decoded+clipped boxes (pre-sort order)
    __shared__ float s_key[NPAD];        // masked score (sort key)
    __shared__ int   s_idx[NPAD];        // payload: original index
    __shared__ float s_sbox[NPROP * 4];  // boxes in sorted order
    __shared__ unsigned char s_keep[NPAD];
    __shared__ int   s_list[TOPK];
    __shared__ int   s_cnt;

    const float img_h = read_dim(p_img_h);
    const float img_w = read_dim(p_img_w);

    // ---- per-proposal: softmax score for class c, decode, clip, validity ----
    if (tid < NPROP) {
        const float* row = class_logit + tid * NCLS;
        float m = row[0];
        #pragma unroll 13
        for (int j = 1; j < NCLS; ++j) m = fmaxf(m, row[j]);
        float ssum = 0.0f;
        #pragma unroll 13
        for (int j = 0; j < NCLS; ++j) ssum += expf(row[j] - m);
        const float score = expf(row[c] - m) / ssum;

        const float x1 = proposal[tid * 4 + 0];
        const float y1 = proposal[tid * 4 + 1];
        const float x2 = proposal[tid * 4 + 2];
        const float y2 = proposal[tid * 4 + 3];
        const float w  = x2 - x1;
        const float h  = y2 - y1;
        const float cx = x1 + 0.5f * w;
        const float cy = y1 + 0.5f * h;

        const float* d = box_reg + tid * (NCLS * 4) + c * 4;
        const float dx = d[0] * 0.1f;
        const float dy = d[1] * 0.1f;
        const float dw = fminf(d[2] * 0.2f, BBOX_CLIP);
        const float dh = fminf(d[3] * 0.2f, BBOX_CLIP);

        const float pcx = dx * w + cx;
        const float pcy = dy * h + cy;
        const float pw  = expf(dw) * w;
        const float ph  = expf(dh) * h;

        float bx1 = pcx - 0.5f * pw;
        float by1 = pcy - 0.5f * ph;
        float bx2 = pcx + 0.5f * pw;
        float by2 = pcy + 0.5f * ph;

        bx1 = fminf(fmaxf(bx1, 0.0f), img_w);
        by1 = fminf(fmaxf(by1, 0.0f), img_h);
        bx2 = fminf(fmaxf(bx2, 0.0f), img_w);
        by2 = fminf(fmaxf(by2, 0.0f), img_h);

        const float bw = bx2 - bx1;
        const float bh = by2 - by1;
        const bool valid = (score >= SCORE_TH) && (bw >= MIN_SIZE) && (bh >= MIN_SIZE);

        s_box[tid * 4 + 0] = bx1;
        s_box[tid * 4 + 1] = by1;
        s_box[tid * 4 + 2] = bx2;
        s_box[tid * 4 + 3] = by2;
        s_key[tid] = valid ? score : -1.0f;
        s_idx[tid] = tid;
    } else {
        s_key[tid] = -2.0f;   // padding sinks below all real entries (incl. -1)
        s_idx[tid] = tid;
    }
    __syncthreads();

    // ---- bitonic sort, 1024 elems: descending score, ties -> ascending idx ----
    for (int k = 2; k <= NPAD; k <<= 1) {
        for (int j = k >> 1; j > 0; j >>= 1) {
            const int ixj = tid ^ j;
            if (ixj > tid) {
                const float k0 = s_key[tid], k1 = s_key[ixj];
                const int   i0 = s_idx[tid], i1 = s_idx[ixj];
                // "after" in final (descending) order
                const bool after = (k0 < k1) || (k0 == k1 && i0 > i1);
                const bool doswap = ((tid & k) == 0) ? after : !after;
                if (doswap) {
                    s_key[tid] = k1; s_key[ixj] = k0;
                    s_idx[tid] = i1; s_idx[ixj] = i0;
                }
            }
            __syncthreads();
        }
    }

    // ---- gather boxes into sorted order; init keep = valid ----
    if (tid < NPROP) {
        const int src = s_idx[tid];     // always < NPROP (padding keys sank)
        s_sbox[tid * 4 + 0] = s_box[src * 4 + 0];
        s_sbox[tid * 4 + 1] = s_box[src * 4 + 1];
        s_sbox[tid * 4 + 2] = s_box[src * 4 + 2];
        s_sbox[tid * 4 + 3] = s_box[src * 4 + 3];
    }
    s_keep[tid] = (s_key[tid] >= 0.0f) ? 1 : 0;
    __syncthreads();

    // ---- greedy NMS. keep flags are monotone (1 -> 0), so iterations where
    // keep[i]==0 can be skipped without a barrier; barrier only after a
    // suppression round actually writes. ----
    for (int i = 0; i < NPROP - 1; ++i) {
        if (!s_keep[i]) continue;       // uniform read, finalized value
        const float ax1 = s_sbox[i * 4 + 0];
        const float ay1 = s_sbox[i * 4 + 1];
        const float ax2 = s_sbox[i * 4 + 2];
        const float ay2 = s_sbox[i * 4 + 3];
        const float area_a = (ax2 - ax1) * (ay2 - ay1);

        const int j = tid;
        if (j > i && j < NPROP && s_keep[j]) {
            const float bx1 = s_sbox[j * 4 + 0];
            const float by1 = s_sbox[j * 4 + 1];
            const float bx2 = s_sbox[j * 4 + 2];
            const float by2 = s_sbox[j * 4 + 3];
            const float area_b = (bx2 - bx1) * (by2 - by1);
            const float lx = fmaxf(ax1, bx1);
            const float ly = fmaxf(ay1, by1);
            const float rx = fminf(ax2, bx2);
            const float ry = fminf(ay2, by2);
            const float iw = fmaxf(rx - lx, 0.0f);
            const float ih = fmaxf(ry - ly, 0.0f);
            const float inter = iw * ih;
            const float uni   = fmaxf(area_a + area_b - inter, 1e-6f);
            if (inter / uni > NMS_TH) s_keep[j] = 0;
        }
        __syncthreads();
    }

    // ---- compact first TOPK kept (they are already in descending order) ----
    if (tid == 0) {
        int cnt = 0;
        for (int i = 0; i < NPROP && cnt < TOPK; ++i)
            if (s_keep[i]) s_list[cnt++] = i;
        s_cnt = cnt;
    }
    __syncthreads();

    // ---- write output: dets [9000,5] then labels [9000] (as float) ----
    if (tid < TOPK) {
        const int r = (c - 1) * TOPK + tid;
        float b0 = 0.f, b1 = 0.f, b2 = 0.f, b3 = 0.f, sc = 0.f, lab = 0.f;
        if (tid < s_cnt) {
            const int j = s_list[tid];
            b0 = s_sbox[j * 4 + 0];
            b1 = s_sbox[j * 4 + 1];
            b2 = s_sbox[j * 4 + 2];
            b3 = s_sbox[j * 4 + 3];
            sc = s_key[j];
            lab = (float)c;
        }
        out[r * 5 + 0] = b0;
        out[r * 5 + 1] = b1;
        out[r * 5 + 2] = b2;
        out[r * 5 + 3] = b3;
        out[r * 5 + 4] = sc;
        const int dets_elems = (NCLS - 1) * TOPK * 5;        // 45000
        if (out_size >= dets_elems + (NCLS - 1) * TOPK)
            out[dets_elems + r] = lab;
    }
}

extern "C" void kernel_launch(void* const* d_in, const int* in_sizes, int n_in,
                              void* d_out, int out_size)
{
    const float* class_logit = (const float*)d_in[0];
    const float* box_reg     = (const float*)d_in[1];
    const float* proposal    = (const float*)d_in[2];
    const void*  img_h       = d_in[3];
    const void*  img_w       = d_in[4];
    (void)in_sizes; (void)n_in;

    roi_heads_kernel<<<NCLS - 1, NPAD>>>(class_logit, box_reg, proposal,
                                         img_h, img_w,
                                         (float*)d_out, out_size);
}

// round 4
// speedup vs baseline: 4.5451x; 4.5451x over previous
#include <cuda_runtime.h>
#include <math.h>

#define NPROP 1000
#define NCLS  91
#define TOPK  100
#define NMAX  1024
#define BLK   256
#define SCORE_TH 0.05f
#define NMS_TH   0.5f
#define MIN_SIZE 1.0f
#define BBOX_CLIP 4.1351665567423f   /* log(1000/16) */

// scratch: per-row softmax stats (max, 1/sum_exp)
__device__ float2 g_stats[NPROP];

__device__ __forceinline__ float read_dim(const void* p) {
    // image_h / image_w may arrive as int32, int64 (low word), or float32.
    int iv = *(const int*)p;
    if (iv >= 1 && iv <= 100000) return (float)iv;
    float fv = __int_as_float(iv);
    if (fv >= 1.0f && fv <= 100000.0f) return fv;
    return (float)iv;
}

// ---------------- kernel A: per-row softmax stats ----------------
__global__ void softmax_stats_kernel(const float* __restrict__ class_logit)
{
    const int r = blockIdx.x * blockDim.x + threadIdx.x;
    if (r >= NPROP) return;
    const float* row = class_logit + r * NCLS;
    float m = row[0];
    #pragma unroll 13
    for (int j = 1; j < NCLS; ++j) m = fmaxf(m, row[j]);
    float s = 0.0f;
    #pragma unroll 13
    for (int j = 0; j < NCLS; ++j) s += expf(row[j] - m);
    g_stats[r] = make_float2(m, 1.0f / s);
}

// ---------------- kernel B: per-class decode + NMS + top-K ----------------
__global__ __launch_bounds__(BLK, 1)
void roi_main_kernel(const float* __restrict__ class_logit,   // [N, C]
                     const float* __restrict__ box_reg,       // [N, C*4]
                     const float* __restrict__ proposal,      // [N, 4]
                     const void*  __restrict__ p_img_h,
                     const void*  __restrict__ p_img_w,
                     float* __restrict__ out, int out_size)
{
    const int c   = blockIdx.x + 1;     // foreground class 1..90
    const int tid = threadIdx.x;

    __shared__ unsigned long long s_key[NMAX]; // (score_bits<<32)|(NPROP - idx)
    __shared__ int    s_slot[NMAX];            // payload -> compact box slot
    __shared__ float4 s_cbox[NMAX];            // compacted boxes (slot order)
    __shared__ float4 s_sbox[NMAX];            // boxes in sorted order
    __shared__ unsigned char s_keep[NMAX];
    __shared__ int    s_list[TOPK];
    __shared__ int    s_mcnt;                  // compact counter
    __shared__ int    s_cnt;                   // kept count

    const float img_h = read_dim(p_img_h);
    const float img_w = read_dim(p_img_w);

    if (tid == 0) s_mcnt = 0;
    __syncthreads();

    // ---- decode + filter + compact (only valid entries survive) ----
    for (int p = tid; p < NPROP; p += BLK) {
        const float  lc = class_logit[p * NCLS + c];
        const float2 st = g_stats[p];
        const float  score = expf(lc - st.x) * st.y;

        const float4 pr = ((const float4*)proposal)[p];
        const float w  = pr.z - pr.x;
        const float h  = pr.w - pr.y;
        const float cx = pr.x + 0.5f * w;
        const float cy = pr.y + 0.5f * h;

        const float4 d = *(const float4*)(box_reg + p * (NCLS * 4) + c * 4);
        const float dx = d.x * 0.1f;
        const float dy = d.y * 0.1f;
        const float dw = fminf(d.z * 0.2f, BBOX_CLIP);
        const float dh = fminf(d.w * 0.2f, BBOX_CLIP);

        const float pcx = dx * w + cx;
        const float pcy = dy * h + cy;
        const float pw  = expf(dw) * w;
        const float ph  = expf(dh) * h;

        float bx1 = fminf(fmaxf(pcx - 0.5f * pw, 0.0f), img_w);
        float by1 = fminf(fmaxf(pcy - 0.5f * ph, 0.0f), img_h);
        float bx2 = fminf(fmaxf(pcx + 0.5f * pw, 0.0f), img_w);
        float by2 = fminf(fmaxf(pcy + 0.5f * ph, 0.0f), img_h);

        const bool valid = (score >= SCORE_TH) &&
                           (bx2 - bx1 >= MIN_SIZE) && (by2 - by1 >= MIN_SIZE);
        if (valid) {
            const int slot = atomicAdd(&s_mcnt, 1);
            s_cbox[slot] = make_float4(bx1, by1, bx2, by2);
            // deterministic total order: score desc, original idx asc
            s_key[slot] = ((unsigned long long)__float_as_uint(score) << 32)
                        | (unsigned int)(NPROP - p);
        }
    }
    __syncthreads();

    const int M = s_mcnt;
    int Mpad = 2;
    if (M > 2) Mpad = 1 << (32 - __clz(M - 1));   // next pow2 >= M

    for (int i = tid; i < Mpad; i += BLK) {
        if (i >= M) s_key[i] = 0ULL;              // sinks below all valid
        s_slot[i] = i;
    }
    __syncthreads();

    // ---- bitonic sort of Mpad elems, descending on 64-bit key ----
    for (int k = 2; k <= Mpad; k <<= 1) {
        for (int j = k >> 1; j > 0; j >>= 1) {
            for (int i = tid; i < Mpad; i += BLK) {
                const int ixj = i ^ j;
                if (ixj > i) {
                    const unsigned long long k0 = s_key[i], k1 = s_key[ixj];
                    const bool desc = ((i & k) == 0);
                    if (desc ? (k0 < k1) : (k0 > k1)) {
                        s_key[i] = k1; s_key[ixj] = k0;
                        const int t = s_slot[i]; s_slot[i] = s_slot[ixj]; s_slot[ixj] = t;
                    }
                }
            }
            __syncthreads();
        }
    }

    // ---- gather boxes into sorted order; init keep flags ----
    for (int i = tid; i < M; i += BLK) s_sbox[i] = s_cbox[s_slot[i]];
    for (int i = tid; i < Mpad; i += BLK) s_keep[i] = (i < M) ? 1 : 0;
    __syncthreads();

    // ---- greedy NMS over M entries (monotone keep -> skip w/o barrier) ----
    for (int i = 0; i < M - 1; ++i) {
        if (!s_keep[i]) continue;
        const float4 a = s_sbox[i];
        const float area_a = (a.z - a.x) * (a.w - a.y);

        for (int j = i + 1 + tid; j < M; j += BLK) {
            if (!s_keep[j]) continue;
            const float4 b = s_sbox[j];
            const float area_b = (b.z - b.x) * (b.w - b.y);
            const float iw = fmaxf(fminf(a.z, b.z) - fmaxf(a.x, b.x), 0.0f);
            const float ih = fmaxf(fminf(a.w, b.w) - fmaxf(a.y, b.y), 0.0f);
            const float inter = iw * ih;
            const float uni   = fmaxf(area_a + area_b - inter, 1e-6f);
            if (inter > NMS_TH * uni) s_keep[j] = 0;
        }
        __syncthreads();
    }

    // ---- compact first TOPK kept (already in descending order) ----
    if (tid == 0) {
        int cnt = 0;
        for (int i = 0; i < M && cnt < TOPK; ++i)
            if (s_keep[i]) s_list[cnt++] = i;
        s_cnt = cnt;
    }
    __syncthreads();

    // ---- write output: dets [9000,5] then labels [9000] (as float) ----
    if (tid < TOPK) {
        const int r = (c - 1) * TOPK + tid;
        float b0 = 0.f, b1 = 0.f, b2 = 0.f, b3 = 0.f, sc = 0.f, lab = 0.f;
        if (tid < s_cnt) {
            const int j = s_list[tid];
            const float4 b = s_sbox[j];
            b0 = b.x; b1 = b.y; b2 = b.z; b3 = b.w;
            sc = __uint_as_float((unsigned int)(s_key[j] >> 32));
            lab = (float)c;
        }
        out[r * 5 + 0] = b0;
        out[r * 5 + 1] = b1;
        out[r * 5 + 2] = b2;
        out[r * 5 + 3] = b3;
        out[r * 5 + 4] = sc;
        const int dets_elems = (NCLS - 1) * TOPK * 5;        // 45000
        if (out_size >= dets_elems + (NCLS - 1) * TOPK)
            out[dets_elems + r] = lab;
    }
}

extern "C" void kernel_launch(void* const* d_in, const int* in_sizes, int n_in,
                              void* d_out, int out_size)
{
    const float* class_logit = (const float*)d_in[0];
    const float* box_reg     = (const float*)d_in[1];
    const float* proposal    = (const float*)d_in[2];
    const void*  img_h       = d_in[3];
    const void*  img_w       = d_in[4];
    (void)in_sizes; (void)n_in;

    softmax_stats_kernel<<<(NPROP + 255) / 256, 256>>>(class_logit);
    roi_main_kernel<<<NCLS - 1, BLK>>>(class_logit, box_reg, proposal,
                                       img_h, img_w,
                                       (float*)d_out, out_size);
}

// round 5
// speedup vs baseline: 7.3265x; 1.6119x over previous
#include <cuda_runtime.h>
#include <math.h>

#define NPROP 1000
#define NCLS  91
#define TOPK  100
#define NMAX  1024
#define MCAP  256          /* fast bitmask-NMS path capacity */
#define BLK   256
#define SCORE_TH 0.05f
#define NMS_TH   0.5f
#define MIN_SIZE 1.0f
#define BBOX_CLIP 4.1351665567423f   /* log(1000/16) */

// scratch: per-row softmax stats (max, 1/sum_exp)
__device__ float2 g_stats[NPROP];

__device__ __forceinline__ float read_dim(const void* p) {
    int iv = *(const int*)p;
    if (iv >= 1 && iv <= 100000) return (float)iv;        // int32 / int64 low word
    float fv = __int_as_float(iv);
    if (fv >= 1.0f && fv <= 100000.0f) return fv;          // float32
    return (float)iv;
}

// ---------------- kernel A: per-row softmax stats (warp per row) ----------------
__global__ void softmax_stats_kernel(const float* __restrict__ class_logit)
{
    const int gtid = blockIdx.x * blockDim.x + threadIdx.x;
    const int row  = gtid >> 5;
    const int lane = gtid & 31;
    if (row >= NPROP) return;
    const float* r = class_logit + row * NCLS;

    float m = -3.4e38f;
    #pragma unroll
    for (int j = lane; j < NCLS; j += 32) m = fmaxf(m, r[j]);
    #pragma unroll
    for (int o = 16; o; o >>= 1) m = fmaxf(m, __shfl_xor_sync(0xffffffffu, m, o));

    float s = 0.0f;
    #pragma unroll
    for (int j = lane; j < NCLS; j += 32) s += expf(r[j] - m);
    #pragma unroll
    for (int o = 16; o; o >>= 1) s += __shfl_xor_sync(0xffffffffu, s, o);

    if (lane == 0) g_stats[row] = make_float2(m, 1.0f / s);
}

// ---------------- kernel B: per-class decode + sort + NMS + top-K ----------------
__global__ __launch_bounds__(BLK, 1)
void roi_main_kernel(const float* __restrict__ class_logit,   // [N, C]
                     const float* __restrict__ box_reg,       // [N, C*4]
                     const float* __restrict__ proposal,      // [N, 4]
                     const void*  __restrict__ p_img_h,
                     const void*  __restrict__ p_img_w,
                     float* __restrict__ out, int out_size)
{
    const int c   = blockIdx.x + 1;     // foreground class 1..90
    const int tid = threadIdx.x;

    __shared__ unsigned long long s_key[NMAX];     // (score_bits<<32)|(NPROP-idx)
    __shared__ int    s_slot[NMAX];                // payload -> compact box slot
    __shared__ float4 s_cbox[NMAX];                // compacted boxes (slot order)
    __shared__ float4 s_sb[MCAP];                  // sorted boxes (fast path)
    __shared__ unsigned long long s_mask[MCAP * 4];// suppression bitmatrix
    __shared__ unsigned char s_keep[NMAX];         // fallback path only
    __shared__ int    s_list[TOPK];
    __shared__ int    s_mcnt;
    __shared__ int    s_cnt;

    const float img_h = read_dim(p_img_h);
    const float img_w = read_dim(p_img_w);

    if (tid == 0) s_mcnt = 0;
    __syncthreads();

    // ---- decode + filter + compact ----
    for (int p = tid; p < NPROP; p += BLK) {
        const float  lc = class_logit[p * NCLS + c];
        const float2 st = g_stats[p];
        const float  score = expf(lc - st.x) * st.y;

        const float4 pr = ((const float4*)proposal)[p];
        const float w  = pr.z - pr.x;
        const float h  = pr.w - pr.y;
        const float cx = pr.x + 0.5f * w;
        const float cy = pr.y + 0.5f * h;

        const float4 d = *(const float4*)(box_reg + p * (NCLS * 4) + c * 4);
        const float dx = d.x * 0.1f;
        const float dy = d.y * 0.1f;
        const float dw = fminf(d.z * 0.2f, BBOX_CLIP);
        const float dh = fminf(d.w * 0.2f, BBOX_CLIP);

        const float pcx = dx * w + cx;
        const float pcy = dy * h + cy;
        const float pw  = expf(dw) * w;
        const float ph  = expf(dh) * h;

        float bx1 = fminf(fmaxf(pcx - 0.5f * pw, 0.0f), img_w);
        float by1 = fminf(fmaxf(pcy - 0.5f * ph, 0.0f), img_h);
        float bx2 = fminf(fmaxf(pcx + 0.5f * pw, 0.0f), img_w);
        float by2 = fminf(fmaxf(pcy + 0.5f * ph, 0.0f), img_h);

        const bool valid = (score >= SCORE_TH) &&
                           (bx2 - bx1 >= MIN_SIZE) && (by2 - by1 >= MIN_SIZE);
        if (valid) {
            const int slot = atomicAdd(&s_mcnt, 1);
            s_cbox[slot] = make_float4(bx1, by1, bx2, by2);
            s_key[slot] = ((unsigned long long)__float_as_uint(score) << 32)
                        | (unsigned int)(NPROP - p);
        }
    }
    __syncthreads();

    const int M = s_mcnt;
    int Mpad = 2;
    if (M > 2) Mpad = 1 << (32 - __clz(M - 1));   // next pow2 >= M

    for (int i = tid; i < Mpad; i += BLK) {
        if (i >= M) s_key[i] = 0ULL;              // sinks below all valid
        s_slot[i] = i;
    }
    __syncthreads();

    // ---- bitonic sort of Mpad elems, descending on 64-bit key ----
    for (int k = 2; k <= Mpad; k <<= 1) {
        for (int j = k >> 1; j > 0; j >>= 1) {
            for (int i = tid; i < Mpad; i += BLK) {
                const int ixj = i ^ j;
                if (ixj > i) {
                    const unsigned long long k0 = s_key[i], k1 = s_key[ixj];
                    const bool desc = ((i & k) == 0);
                    if (desc ? (k0 < k1) : (k0 > k1)) {
                        s_key[i] = k1; s_key[ixj] = k0;
                        const int t = s_slot[i]; s_slot[i] = s_slot[ixj]; s_slot[ixj] = t;
                    }
                }
            }
            __syncthreads();
        }
    }

    const bool fast = (M <= MCAP);

    if (fast) {
        // ---- materialize sorted boxes ----
        for (int i = tid; i < M; i += BLK) s_sb[i] = s_cbox[s_slot[i]];
        __syncthreads();

        // ---- parallel suppression bitmatrix: bit (i, j) iff IoU>th && j>i ----
        const int nw = (M + 63) >> 6;
        for (int t = tid; t < M * nw; t += BLK) {
            const int i = t / nw;
            const int w = t - i * nw;
            const float4 a = s_sb[i];
            const float area_a = (a.z - a.x) * (a.w - a.y);
            unsigned long long bits = 0ULL;
            const int jbase = w << 6;
            const int jend  = min(jbase + 64, M);
            for (int j = max(jbase, i + 1); j < jend; ++j) {
                const float4 b = s_sb[j];
                const float area_b = (b.z - b.x) * (b.w - b.y);
                const float iw = fmaxf(fminf(a.z, b.z) - fmaxf(a.x, b.x), 0.0f);
                const float ih = fmaxf(fminf(a.w, b.w) - fmaxf(a.y, b.y), 0.0f);
                const float inter = iw * ih;
                const float uni   = fmaxf(area_a + area_b - inter, 1e-6f);
                if (inter > NMS_TH * uni) bits |= 1ULL << (j - jbase);
            }
            s_mask[i * 4 + w] = bits;
        }
        __syncthreads();

        // ---- serial greedy scan, removed-set in registers, no barriers ----
        if (tid == 0) {
            unsigned long long rem0 = 0, rem1 = 0, rem2 = 0, rem3 = 0;
            int cnt = 0;
            for (int i = 0; i < M && cnt < TOPK; ++i) {
                unsigned long long rw = (i < 64) ? rem0 : (i < 128) ? rem1
                                    : (i < 192) ? rem2 : rem3;
                if (!((rw >> (i & 63)) & 1ULL)) {
                    s_list[cnt++] = i;
                    rem0 |= s_mask[i * 4 + 0];
                    rem1 |= s_mask[i * 4 + 1];
                    rem2 |= s_mask[i * 4 + 2];
                    rem3 |= s_mask[i * 4 + 3];
                }
            }
            s_cnt = cnt;
        }
        __syncthreads();
    } else {
        // ---- fallback: barrier-per-round NMS (correct for any M) ----
        for (int i = tid; i < Mpad; i += BLK) s_keep[i] = (i < M) ? 1 : 0;
        __syncthreads();
        for (int i = 0; i < M - 1; ++i) {
            if (!s_keep[i]) continue;
            const float4 a = s_cbox[s_slot[i]];
            const float area_a = (a.z - a.x) * (a.w - a.y);
            for (int j = i + 1 + tid; j < M; j += BLK) {
                if (!s_keep[j]) continue;
                const float4 b = s_cbox[s_slot[j]];
                const float area_b = (b.z - b.x) * (b.w - b.y);
                const float iw = fmaxf(fminf(a.z, b.z) - fmaxf(a.x, b.x), 0.0f);
                const float ih = fmaxf(fminf(a.w, b.w) - fmaxf(a.y, b.y), 0.0f);
                const float inter = iw * ih;
                const float uni   = fmaxf(area_a + area_b - inter, 1e-6f);
                if (inter > NMS_TH * uni) s_keep[j] = 0;
            }
            __syncthreads();
        }
        if (tid == 0) {
            int cnt = 0;
            for (int i = 0; i < M && cnt < TOPK; ++i)
                if (s_keep[i]) s_list[cnt++] = i;
            s_cnt = cnt;
        }
        __syncthreads();
    }

    // ---- write output: dets [9000,5] then labels [9000] (as float) ----
    if (tid < TOPK) {
        const int r = (c - 1) * TOPK + tid;
        float b0 = 0.f, b1 = 0.f, b2 = 0.f, b3 = 0.f, sc = 0.f, lab = 0.f;
        if (tid < s_cnt) {
            const int j = s_list[tid];
            const float4 b = fast ? s_sb[j] : s_cbox[s_slot[j]];
            b0 = b.x; b1 = b.y; b2 = b.z; b3 = b.w;
            sc = __uint_as_float((unsigned int)(s_key[j] >> 32));
            lab = (float)c;
        }
        out[r * 5 + 0] = b0;
        out[r * 5 + 1] = b1;
        out[r * 5 + 2] = b2;
        out[r * 5 + 3] = b3;
        out[r * 5 + 4] = sc;
        const int dets_elems = (NCLS - 1) * TOPK * 5;        // 45000
        if (out_size >= dets_elems + (NCLS - 1) * TOPK)
            out[dets_elems + r] = lab;
    }
}

extern "C" void kernel_launch(void* const* d_in, const int* in_sizes, int n_in,
                              void* d_out, int out_size)
{
    const float* class_logit = (const float*)d_in[0];
    const float* box_reg     = (const float*)d_in[1];
    const float* proposal    = (const float*)d_in[2];
    const void*  img_h       = d_in[3];
    const void*  img_w       = d_in[4];
    (void)in_sizes; (void)n_in;

    softmax_stats_kernel<<<(NPROP * 32 + 255) / 256, 256>>>(class_logit);
    roi_main_kernel<<<NCLS - 1, BLK>>>(class_logit, box_reg, proposal,
                                       img_h, img_w,
                                       (float*)d_out, out_size);
}

// round 6
// speedup vs baseline: 9.8421x; 1.3434x over previous
#include <cuda_runtime.h>
#include <math.h>

#define NPROP 1000
#define NCLS  91
#define TOPK  100
#define NMAX  1024
#define MCAP  256          /* fast bitmask-NMS path capacity */
#define BLK   256
#define SCORE_TH 0.05f
#define NMS_TH   0.5f
#define MIN_SIZE 1.0f
#define BBOX_CLIP 4.1351665567423f   /* log(1000/16) */

// scratch: per-row softmax stats (max, 1/sum_exp) and proposal geometry (w,h,cx,cy)
__device__ float2 g_stats[NPROP];
__device__ float4 g_prop[NPROP];

__device__ __forceinline__ float read_dim(const void* p) {
    int iv = *(const int*)p;
    if (iv >= 1 && iv <= 100000) return (float)iv;        // int32 / int64 low word
    float fv = __int_as_float(iv);
    if (fv >= 1.0f && fv <= 100000.0f) return fv;          // float32
    return (float)iv;
}

// ------------- kernel A: per-row softmax stats + proposal geometry -------------
__global__ void softmax_stats_kernel(const float* __restrict__ class_logit,
                                     const float* __restrict__ proposal)
{
    const int gtid = blockIdx.x * blockDim.x + threadIdx.x;
    const int row  = gtid >> 5;
    const int lane = gtid & 31;
    if (row >= NPROP) return;
    const float* r = class_logit + row * NCLS;

    float m = -3.4e38f;
    #pragma unroll
    for (int j = lane; j < NCLS; j += 32) m = fmaxf(m, r[j]);
    #pragma unroll
    for (int o = 16; o; o >>= 1) m = fmaxf(m, __shfl_xor_sync(0xffffffffu, m, o));

    float s = 0.0f;
    #pragma unroll
    for (int j = lane; j < NCLS; j += 32) s += expf(r[j] - m);
    #pragma unroll
    for (int o = 16; o; o >>= 1) s += __shfl_xor_sync(0xffffffffu, s, o);

    if (lane == 0) {
        g_stats[row] = make_float2(m, 1.0f / s);
        const float4 pr = ((const float4*)proposal)[row];
        const float w = pr.z - pr.x;
        const float h = pr.w - pr.y;
        g_prop[row] = make_float4(w, h, pr.x + 0.5f * w, pr.y + 0.5f * h);
    }
}

// ------------- kernel B: per-class score-filter + decode + sort + NMS + top-K -------------
__global__ __launch_bounds__(BLK, 1)
void roi_main_kernel(const float* __restrict__ class_logit,   // [N, C]
                     const float* __restrict__ box_reg,       // [N, C*4]
                     const void*  __restrict__ p_img_h,
                     const void*  __restrict__ p_img_w,
                     float* __restrict__ out, int out_size)
{
    const int c   = blockIdx.x + 1;     // foreground class 1..90
    const int tid = threadIdx.x;

    __shared__ unsigned long long s_key[NMAX];     // (score_bits<<32)|(NPROP-idx)
    __shared__ float4 s_cbox[NMAX];                // decoded boxes (compact order)
    __shared__ int    s_perm[NMAX];                // sorted pos -> compact slot
    __shared__ int    s_p[NMAX];                   // compact slot -> proposal idx
    __shared__ unsigned long long s_mask[MCAP * 4];// suppression bitmatrix
    __shared__ unsigned char s_keep[NMAX];         // fallback path only
    __shared__ int    s_list[TOPK];
    __shared__ int    s_mcnt, s_drop, s_cnt;

    const float img_h = read_dim(p_img_h);
    const float img_w = read_dim(p_img_w);

    if (tid == 0) { s_mcnt = 0; s_drop = 0; }
    __syncthreads();

    // ---- phase 1: score-only prefilter + compact ----
    for (int p = tid; p < NPROP; p += BLK) {
        const float  lc = class_logit[p * NCLS + c];
        const float2 st = g_stats[p];
        const float  score = expf(lc - st.x) * st.y;
        if (score >= SCORE_TH) {
            const int slot = atomicAdd(&s_mcnt, 1);
            s_p[slot]   = p;
            s_key[slot] = ((unsigned long long)__float_as_uint(score) << 32)
                        | (unsigned int)(NPROP - p);
        }
    }
    __syncthreads();

    const int M = s_mcnt;

    // ---- phase 2: decode + clip only the survivors ----
    for (int i = tid; i < M; i += BLK) {
        const int p = s_p[i];
        const float4 g = g_prop[p];        // w, h, cx, cy
        const float4 d = *(const float4*)(box_reg + p * (NCLS * 4) + c * 4);
        const float dx = d.x * 0.1f;
        const float dy = d.y * 0.1f;
        const float dw = fminf(d.z * 0.2f, BBOX_CLIP);
        const float dh = fminf(d.w * 0.2f, BBOX_CLIP);

        const float pcx = dx * g.x + g.z;
        const float pcy = dy * g.y + g.w;
        const float pw  = expf(dw) * g.x;
        const float ph  = expf(dh) * g.y;

        const float bx1 = fminf(fmaxf(pcx - 0.5f * pw, 0.0f), img_w);
        const float by1 = fminf(fmaxf(pcy - 0.5f * ph, 0.0f), img_h);
        const float bx2 = fminf(fmaxf(pcx + 0.5f * pw, 0.0f), img_w);
        const float by2 = fminf(fmaxf(pcy + 0.5f * ph, 0.0f), img_h);

        s_cbox[i] = make_float4(bx1, by1, bx2, by2);
        if (bx2 - bx1 < MIN_SIZE || by2 - by1 < MIN_SIZE) {
            // demote: score bits 0, unique low word -> sinks below all valid keys
            s_key[i] = (unsigned long long)(unsigned int)(NPROP - p);
            atomicAdd(&s_drop, 1);
        }
    }
    __syncthreads();

    const int Meff = M - s_drop;

    // ---- phase 3: rank sort (keys unique -> ranks are a bijection) ----
    for (int i = tid; i < M; i += BLK) {
        const unsigned long long ki = s_key[i];
        int r = 0;
        for (int j = 0; j < M; ++j) r += (s_key[j] > ki);
        s_perm[r] = i;
    }
    __syncthreads();

    const bool fast = (Meff <= MCAP);

    if (fast) {
        // ---- suppression bitmatrix over sorted positions (4 words/row) ----
        for (int t = tid; t < Meff * 4; t += BLK) {
            const int i = t >> 2;
            const int w = t & 3;
            unsigned long long bits = 0ULL;
            const int jbase = w << 6;
            const int jend  = min(jbase + 64, Meff);
            if (jend > i + 1) {
                const float4 a = s_cbox[s_perm[i]];
                const float area_a = (a.z - a.x) * (a.w - a.y);
                for (int j = max(jbase, i + 1); j < jend; ++j) {
                    const float4 b = s_cbox[s_perm[j]];
                    const float area_b = (b.z - b.x) * (b.w - b.y);
                    const float iw = fmaxf(fminf(a.z, b.z) - fmaxf(a.x, b.x), 0.0f);
                    const float ih = fmaxf(fminf(a.w, b.w) - fmaxf(a.y, b.y), 0.0f);
                    const float inter = iw * ih;
                    const float uni   = fmaxf(area_a + area_b - inter, 1e-6f);
                    if (inter > NMS_TH * uni) bits |= 1ULL << (j - jbase);
                }
            }
            s_mask[t] = bits;
        }
        __syncthreads();

        // ---- serial greedy scan: jump directly to next kept via ffs ----
        if (tid == 0) {
            unsigned long long rem0 = 0, rem1 = 0, rem2 = 0, rem3 = 0;
            int cnt = 0;
            const int nw = (Meff + 63) >> 6;
            for (int w = 0; w < nw && cnt < TOPK; ++w) {
                unsigned long long rw = (w == 0) ? rem0 : (w == 1) ? rem1
                                      : (w == 2) ? rem2 : rem3;
                unsigned long long avail = ~rw;
                if ((w << 6) + 64 > Meff)
                    avail &= (1ULL << (Meff & 63)) - 1ULL;   // Meff&63 != 0 here
                while (avail && cnt < TOPK) {
                    const int b = __ffsll((long long)avail) - 1;
                    const int i = (w << 6) + b;
                    s_list[cnt++] = i;
                    rem0 |= s_mask[i * 4 + 0];
                    rem1 |= s_mask[i * 4 + 1];
                    rem2 |= s_mask[i * 4 + 2];
                    rem3 |= s_mask[i * 4 + 3];
                    const unsigned long long nrw = (w == 0) ? rem0 : (w == 1) ? rem1
                                                 : (w == 2) ? rem2 : rem3;
                    avail &= ~nrw;
                    avail &= (b == 63) ? 0ULL : ~((2ULL << b) - 1ULL);
                }
            }
            s_cnt = cnt;
        }
        __syncthreads();
    } else {
        // ---- fallback: barrier-per-round NMS over sorted order (any M) ----
        for (int i = tid; i < Meff; i += BLK) s_keep[i] = 1;
        __syncthreads();
        for (int i = 0; i < Meff - 1; ++i) {
            if (!s_keep[i]) continue;
            const float4 a = s_cbox[s_perm[i]];
            const float area_a = (a.z - a.x) * (a.w - a.y);
            for (int j = i + 1 + tid; j < Meff; j += BLK) {
                if (!s_keep[j]) continue;
                const float4 b = s_cbox[s_perm[j]];
                const float area_b = (b.z - b.x) * (b.w - b.y);
                const float iw = fmaxf(fminf(a.z, b.z) - fmaxf(a.x, b.x), 0.0f);
                const float ih = fmaxf(fminf(a.w, b.w) - fmaxf(a.y, b.y), 0.0f);
                const float inter = iw * ih;
                const float uni   = fmaxf(area_a + area_b - inter, 1e-6f);
                if (inter > NMS_TH * uni) s_keep[j] = 0;
            }
            __syncthreads();
        }
        if (tid == 0) {
            int cnt = 0;
            for (int i = 0; i < Meff && cnt < TOPK; ++i)
                if (s_keep[i]) s_list[cnt++] = i;
            s_cnt = cnt;
        }
        __syncthreads();
    }

    // ---- write output: dets [9000,5] then labels [9000] (as float) ----
    if (tid < TOPK) {
        const int r = (c - 1) * TOPK + tid;
        float b0 = 0.f, b1 = 0.f, b2 = 0.f, b3 = 0.f, sc = 0.f, lab = 0.f;
        if (tid < s_cnt) {
            const int slot = s_perm[s_list[tid]];
            const float4 b = s_cbox[slot];
            b0 = b.x; b1 = b.y; b2 = b.z; b3 = b.w;
            sc = __uint_as_float((unsigned int)(s_key[slot] >> 32));
            lab = (float)c;
        }
        out[r * 5 + 0] = b0;
        out[r * 5 + 1] = b1;
        out[r * 5 + 2] = b2;
        out[r * 5 + 3] = b3;
        out[r * 5 + 4] = sc;
        const int dets_elems = (NCLS - 1) * TOPK * 5;        // 45000
        if (out_size >= dets_elems + (NCLS - 1) * TOPK)
            out[dets_elems + r] = lab;
    }
}

extern "C" void kernel_launch(void* const* d_in, const int* in_sizes, int n_in,
                              void* d_out, int out_size)
{
    const float* class_logit = (const float*)d_in[0];
    const float* box_reg     = (const float*)d_in[1];
    const float* proposal    = (const float*)d_in[2];
    const void*  img_h       = d_in[3];
    const void*  img_w       = d_in[4];
    (void)in_sizes; (void)n_in;

    softmax_stats_kernel<<<(NPROP * 32 + 255) / 256, 256>>>(class_logit, proposal);
    roi_main_kernel<<<NCLS - 1, BLK>>>(class_logit, box_reg,
                                       img_h, img_w,
                                       (float*)d_out, out_size);
}